// round 8
// baseline (speedup 1.0000x reference)
#include <cuda_runtime.h>
#include <cuda_fp16.h>
#include <math.h>
#include <stdint.h>

// ---------------------------------------------------------------------------
// AttnBlock via mma.sync HMMA (base sm_100 target).
// Single-pass fp16 GEMMs, fp32 accum.
// R8: CTA tile 128x256, warp tile 64x64 (2x4 warp grid) — halves smem
// traffic per MMA (R7 was smem-crossbar bound at tensor=44.7%).
// ---------------------------------------------------------------------------

#define BB   32
#define CC   512
#define SS   1024
#define NGRP 32
#define CPG  16
#define GELEMS (CPG * SS)
#define SCALE_QK 0.044194173824159216f

typedef __half fp16;

// ------------------------------- scratch ----------------------------------
static __device__ float2 g_stats[BB * NGRP];
static __device__ fp16 g_th [(size_t)BB * SS * CC];
static __device__ fp16 g_qh [(size_t)BB * SS * CC];
static __device__ fp16 g_kh [(size_t)BB * SS * CC];
static __device__ fp16 g_vth[(size_t)BB * CC * SS];
static __device__ float g_s [(size_t)BB * SS * SS];
static __device__ fp16 g_ph [(size_t)BB * SS * SS];
static __device__ fp16 g_oh [(size_t)BB * SS * CC];
static __device__ fp16 g_wh [4 * CC * CC];

// ------------------------------ asm helpers --------------------------------
__device__ __forceinline__ uint32_t smem_u32(const void* p) {
    uint32_t a;
    asm("{ .reg .u64 t; cvta.to.shared.u64 t, %1; cvt.u32.u64 %0, t; }" : "=r"(a) : "l"(p));
    return a;
}
#define CP16(dst, src) \
    asm volatile("cp.async.cg.shared.global [%0], [%1], 16;" :: "r"(dst), "l"(src))
#define CP_COMMIT() asm volatile("cp.async.commit_group;" ::: "memory")
#define CP_WAIT(n)  asm volatile("cp.async.wait_group %0;" :: "n"(n) : "memory")

#define LDSM4(r0, r1, r2, r3, addr) \
    asm volatile("ldmatrix.sync.aligned.m8n8.x4.shared.b16 {%0,%1,%2,%3}, [%4];" \
        : "=r"(r0), "=r"(r1), "=r"(r2), "=r"(r3) : "r"(addr))

#define MMA_FP16(d, a, b) \
    asm volatile("mma.sync.aligned.m16n8k16.row.col.f32.f16.f16.f32 " \
        "{%0,%1,%2,%3}, {%4,%5,%6,%7}, {%8,%9}, {%0,%1,%2,%3};" \
        : "+f"((d)[0]), "+f"((d)[1]), "+f"((d)[2]), "+f"((d)[3]) \
        : "r"((a)[0]), "r"((a)[1]), "r"((a)[2]), "r"((a)[3]), \
          "r"((b)[0]), "r"((b)[1]))

// ---------------------------------------------------------------------------
// Warp-MMA batched GEMM: C[m,n] = alpha*(A[m,:] . B[n,:]) + bias[n]
// A [M,K] row-major fp16, B [N,K] row-major fp16.
// CTA tile 128(m) x 256(n), BK=32, 8 warps as 2(m) x 4(n), warp tile 64x64.
// 3-stage cp.async pipeline. 1 CTA/SM (128 acc regs/thread).
// OUT_MODE 0: fp32 C[m,n] -> Cf
// OUT_MODE 1: fp16 C[m,n] -> Ch
// OUT_MODE 2: fp16 C^T[n,m] -> Ch           (ldc strides the n dim)
// OUT_MODE 3: fp32 C^T[n,m] + resid -> Cf   (residual add, ldc strides n)
// smem/stage: A 128x40h (10240 B) + B 256x40h (20480 B) = 30720 B
// ---------------------------------------------------------------------------
#define STAGE_B 30720

template<int OUT_MODE>
__global__ void __launch_bounds__(256, 1)
gemm_mma(const fp16* __restrict__ A, const fp16* __restrict__ B,
         const float* __restrict__ bias, const float* __restrict__ resid,
         float* __restrict__ Cf, fp16* __restrict__ Ch,
         int K, int lda, int ldb, int ldc,
         long long sA, long long sB, long long sC, float alpha)
{
    extern __shared__ __align__(16) char smem[];
    const uint32_t sb = smem_u32(smem);
    const int tid = threadIdx.x, wid = tid >> 5, lane = tid & 31;
    const int bm = blockIdx.y * 128, bn = blockIdx.x * 256;

    A += (size_t)blockIdx.z * sA;
    B += (size_t)blockIdx.z * sB;

    float acc[4][8][4];
    #pragma unroll
    for (int i = 0; i < 4; i++)
        #pragma unroll
        for (int j = 0; j < 8; j++)
            #pragma unroll
            for (int t = 0; t < 4; t++) acc[i][j][t] = 0.f;

    auto load_stage = [&](int k0, int buf) {
        const uint32_t base = sb + buf * STAGE_B;
        #pragma unroll
        for (int i = 0; i < 2; i++) {           // A: 128 rows x 4 segs
            const int t = tid + i * 256;
            const int r = t >> 2, seg = t & 3;
            CP16(base + (uint32_t)(r * 80 + seg * 16),
                 A + (size_t)(bm + r) * lda + k0 + seg * 8);
        }
        #pragma unroll
        for (int i = 0; i < 4; i++) {           // B: 256 rows x 4 segs
            const int t = tid + i * 256;
            const int r = t >> 2, seg = t & 3;
            CP16(base + 10240 + (uint32_t)(r * 80 + seg * 16),
                 B + (size_t)(bn + r) * ldb + k0 + seg * 8);
        }
    };

    const int m0 = (wid & 1) * 64, n0 = (wid >> 1) * 64;
    const int arow = (lane & 7) + ((lane >> 3) & 1) * 8;
    const int acol = (lane >> 4) * 8;
    const int brow = (lane & 7) + (lane >> 4) * 8;
    const int bcol = ((lane >> 3) & 1) * 8;

    const int NC = K >> 5;
    load_stage(0, 0);
    CP_COMMIT();
    if (NC > 1) { load_stage(32, 1); CP_COMMIT(); }

    for (int c = 0; c < NC; c++) {
        if (c + 1 < NC) { CP_WAIT(1); } else { CP_WAIT(0); }
        __syncthreads();
        if (c + 2 < NC) {
            load_stage((c + 2) << 5, (c + 2) % 3);
            CP_COMMIT();
        }

        const uint32_t st = sb + (c % 3) * STAGE_B;
        #pragma unroll
        for (int kx = 0; kx < 32; kx += 16) {
            uint32_t fa[4][4];
            uint32_t fb[8][2];
            #pragma unroll
            for (int mt = 0; mt < 4; mt++) {
                const uint32_t ad = st +
                    (uint32_t)(((m0 + mt * 16 + arow) * 40 + kx + acol) * 2);
                LDSM4(fa[mt][0], fa[mt][1], fa[mt][2], fa[mt][3], ad);
            }
            #pragma unroll
            for (int p = 0; p < 4; p++) {
                const uint32_t bd = st + 10240 +
                    (uint32_t)(((n0 + p * 16 + brow) * 40 + kx + bcol) * 2);
                LDSM4(fb[2*p][0], fb[2*p][1], fb[2*p+1][0], fb[2*p+1][1], bd);
            }
            #pragma unroll
            for (int mt = 0; mt < 4; mt++)
                #pragma unroll
                for (int nt = 0; nt < 8; nt++)
                    MMA_FP16(acc[mt][nt], fa[mt], fb[nt]);
        }
        __syncthreads();
    }

    // ------------------------------ epilogue -------------------------------
    if (OUT_MODE <= 1) {
        #pragma unroll
        for (int mt = 0; mt < 4; mt++) {
            const int gm = bm + m0 + mt * 16 + (lane >> 2);
            #pragma unroll
            for (int nt = 0; nt < 8; nt++) {
                const int gn = bn + n0 + nt * 8 + 2 * (lane & 3);
                const float b0 = bias ? bias[gn]     : 0.f;
                const float b1 = bias ? bias[gn + 1] : 0.f;
                const float* d = acc[mt][nt];
                const float v00 = d[0] * alpha + b0, v01 = d[1] * alpha + b1;
                const float v10 = d[2] * alpha + b0, v11 = d[3] * alpha + b1;
                const size_t r0 = (size_t)blockIdx.z * sC + (size_t)gm * ldc + gn;
                const size_t r1 = r0 + (size_t)8 * ldc;
                if (OUT_MODE == 0) {
                    *reinterpret_cast<float2*>(&Cf[r0]) = make_float2(v00, v01);
                    *reinterpret_cast<float2*>(&Cf[r1]) = make_float2(v10, v11);
                } else {
                    *reinterpret_cast<__half2*>(&Ch[r0]) =
                        __halves2half2(__float2half(v00), __float2half(v01));
                    *reinterpret_cast<__half2*>(&Ch[r1]) =
                        __halves2half2(__float2half(v10), __float2half(v11));
                }
            }
        }
    } else {
        // Transposed epilogue: 4 quarters of 64 n-rows x 128 m-cols in smem.
        float* smt = reinterpret_cast<float*>(smem);      // [64][132] fp32
        const int myq = wid >> 1;
        #pragma unroll
        for (int q = 0; q < 4; q++) {
            __syncthreads();
            if (myq == q) {
                #pragma unroll
                for (int mt = 0; mt < 4; mt++) {
                    const int sl = m0 + mt * 16 + (lane >> 2);
                    #pragma unroll
                    for (int nt = 0; nt < 8; nt++) {
                        const int cl = nt * 8 + 2 * (lane & 3);
                        const float b0 = bias ? bias[bn + q * 64 + cl]     : 0.f;
                        const float b1 = bias ? bias[bn + q * 64 + cl + 1] : 0.f;
                        const float* d = acc[mt][nt];
                        smt[cl       * 132 + sl]     = d[0] * alpha + b0;
                        smt[(cl + 1) * 132 + sl]     = d[1] * alpha + b1;
                        smt[cl       * 132 + sl + 8] = d[2] * alpha + b0;
                        smt[(cl + 1) * 132 + sl + 8] = d[3] * alpha + b1;
                    }
                }
            }
            __syncthreads();
            if (OUT_MODE == 2) {
                #pragma unroll
                for (int it = 0; it < 16; it++) {
                    const int idx = tid + it * 256;
                    const int cl = idx >> 6, s2 = (idx & 63) * 2;
                    const size_t o = (size_t)blockIdx.z * sC +
                        (size_t)(bn + q * 64 + cl) * ldc + bm + s2;
                    *reinterpret_cast<__half2*>(&Ch[o]) = __halves2half2(
                        __float2half(smt[cl * 132 + s2]),
                        __float2half(smt[cl * 132 + s2 + 1]));
                }
            } else {
                #pragma unroll
                for (int it = 0; it < 32; it++) {
                    const int idx = tid + it * 256;
                    const int cl = idx >> 7, sl = idx & 127;
                    const size_t o = (size_t)blockIdx.z * sC +
                        (size_t)(bn + q * 64 + cl) * ldc + bm + sl;
                    Cf[o] = smt[cl * 132 + sl] + resid[o];
                }
            }
        }
    }
}

// ---------------------------------------------------------------------------
// GroupNorm stats
// ---------------------------------------------------------------------------
__global__ __launch_bounds__(256)
void gn_stats_kernel(const float* __restrict__ x, float2* __restrict__ stats)
{
    const int b = blockIdx.x >> 5, g = blockIdx.x & 31;
    const size_t base = ((size_t)b * CC + (size_t)g * CPG) * SS;
    float s = 0.f, s2 = 0.f;
    for (int i = threadIdx.x * 4; i < GELEMS; i += 1024) {
        float4 v = *reinterpret_cast<const float4*>(&x[base + i]);
        s  += v.x + v.y + v.z + v.w;
        s2 += v.x * v.x + v.y * v.y + v.z * v.z + v.w * v.w;
    }
    #pragma unroll
    for (int o = 16; o; o >>= 1) {
        s  += __shfl_xor_sync(0xffffffffu, s, o);
        s2 += __shfl_xor_sync(0xffffffffu, s2, o);
    }
    __shared__ float ws[8], ws2[8];
    if ((threadIdx.x & 31) == 0) { ws[threadIdx.x >> 5] = s; ws2[threadIdx.x >> 5] = s2; }
    __syncthreads();
    if (threadIdx.x == 0) {
        float ts = 0.f, ts2 = 0.f;
        #pragma unroll
        for (int i = 0; i < 8; i++) { ts += ws[i]; ts2 += ws2[i]; }
        const float mu  = ts * (1.f / GELEMS);
        const float var = ts2 * (1.f / GELEMS) - mu * mu;
        stats[blockIdx.x] = make_float2(mu, rsqrtf(var + 1e-6f));
    }
}

// ---------------------------------------------------------------------------
// Normalize + transpose: x[b,c,s] -> t [b,s,c] fp16
// ---------------------------------------------------------------------------
__global__ __launch_bounds__(256)
void norm_t_kernel(const float* __restrict__ x, const float2* __restrict__ stats,
                   const float* __restrict__ w, const float* __restrict__ bgn,
                   fp16* __restrict__ th)
{
    __shared__ float sm[32][33];
    const int b = blockIdx.z, s0 = blockIdx.x * 32, c0 = blockIdx.y * 32;
    const int tx = threadIdx.x, ty = threadIdx.y;
    #pragma unroll
    for (int cy = ty; cy < 32; cy += 8) {
        const int c = c0 + cy;
        const float2 st = stats[b * 32 + (c >> 4)];
        const float v = x[((size_t)b * CC + c) * SS + s0 + tx];
        sm[cy][tx] = (v - st.x) * st.y * w[c] + bgn[c];
    }
    __syncthreads();
    #pragma unroll
    for (int sy = ty; sy < 32; sy += 8)
        th[((size_t)b * SS + s0 + sy) * CC + c0 + tx] = __float2half(sm[tx][sy]);
}

// ---------------------------------------------------------------------------
// Row softmax over 1024 cols; P -> fp16
// ---------------------------------------------------------------------------
__global__ __launch_bounds__(256)
void softmax_kernel(const float* __restrict__ s, fp16* __restrict__ ph)
{
    const size_t ro = (size_t)blockIdx.x * SS;
    float4 v = *reinterpret_cast<const float4*>(&s[ro + threadIdx.x * 4]);

    float m = fmaxf(fmaxf(v.x, v.y), fmaxf(v.z, v.w));
    #pragma unroll
    for (int o = 16; o; o >>= 1) m = fmaxf(m, __shfl_xor_sync(0xffffffffu, m, o));
    __shared__ float redm[8], reds[8];
    const int lane = threadIdx.x & 31, wid = threadIdx.x >> 5;
    if (lane == 0) redm[wid] = m;
    __syncthreads();
    float M = redm[0];
    #pragma unroll
    for (int i = 1; i < 8; i++) M = fmaxf(M, redm[i]);

    v.x = expf(v.x - M); v.y = expf(v.y - M);
    v.z = expf(v.z - M); v.w = expf(v.w - M);
    float sum = v.x + v.y + v.z + v.w;
    #pragma unroll
    for (int o = 16; o; o >>= 1) sum += __shfl_xor_sync(0xffffffffu, sum, o);
    if (lane == 0) reds[wid] = sum;
    __syncthreads();
    float T = 0.f;
    #pragma unroll
    for (int i = 0; i < 8; i++) T += reds[i];
    const float inv = 1.f / T;

    *reinterpret_cast<__half2*>(&ph[ro + threadIdx.x * 4]) =
        __halves2half2(__float2half(v.x * inv), __float2half(v.y * inv));
    *reinterpret_cast<__half2*>(&ph[ro + threadIdx.x * 4 + 2]) =
        __halves2half2(__float2half(v.z * inv), __float2half(v.w * inv));
}

// ---------------------------------------------------------------------------
// All four weight converts in one launch
// ---------------------------------------------------------------------------
__global__ __launch_bounds__(256)
void wconv4_kernel(const float* __restrict__ a, const float* __restrict__ b,
                   const float* __restrict__ c, const float* __restrict__ d,
                   fp16* __restrict__ dst)
{
    const int n = CC * CC;
    for (int i = blockIdx.x * 256 + threadIdx.x; i < n; i += gridDim.x * 256) {
        dst[i]         = __float2half(a[i]);
        dst[n + i]     = __float2half(b[i]);
        dst[2 * n + i] = __float2half(c[i]);
        dst[3 * n + i] = __float2half(d[i]);
    }
}

// ---------------------------------------------------------------------------
// Launch
// ---------------------------------------------------------------------------
extern "C" void kernel_launch(void* const* d_in, const int* in_sizes, int n_in,
                              void* d_out, int out_size)
{
    const float* x   = (const float*)d_in[0];
    const float* gnw = (const float*)d_in[1];
    const float* gnb = (const float*)d_in[2];
    const float* Wq  = (const float*)d_in[3];
    const float* bq  = (const float*)d_in[4];
    const float* Wk  = (const float*)d_in[5];
    const float* bk  = (const float*)d_in[6];
    const float* Wv  = (const float*)d_in[7];
    const float* bv  = (const float*)d_in[8];
    const float* Wo  = (const float*)d_in[9];
    const float* bo  = (const float*)d_in[10];
    float* out = (float*)d_out;

    float2* stats; fp16 *th, *qh, *kh, *vth, *ph, *oh, *wh;
    float *sc;
    cudaGetSymbolAddress((void**)&stats, g_stats);
    cudaGetSymbolAddress((void**)&th,  g_th);
    cudaGetSymbolAddress((void**)&qh,  g_qh);
    cudaGetSymbolAddress((void**)&kh,  g_kh);
    cudaGetSymbolAddress((void**)&vth, g_vth);
    cudaGetSymbolAddress((void**)&sc,  g_s);
    cudaGetSymbolAddress((void**)&ph,  g_ph);
    cudaGetSymbolAddress((void**)&oh,  g_oh);
    cudaGetSymbolAddress((void**)&wh,  g_wh);

    const int SMEM = 3 * STAGE_B;   // 92160 B (>= 64*132*4 epilogue tile)
    cudaFuncSetAttribute(gemm_mma<0>, cudaFuncAttributeMaxDynamicSharedMemorySize, SMEM);
    cudaFuncSetAttribute(gemm_mma<1>, cudaFuncAttributeMaxDynamicSharedMemorySize, SMEM);
    cudaFuncSetAttribute(gemm_mma<2>, cudaFuncAttributeMaxDynamicSharedMemorySize, SMEM);
    cudaFuncSetAttribute(gemm_mma<3>, cudaFuncAttributeMaxDynamicSharedMemorySize, SMEM);

    const long long sSC = (long long)SS * CC;
    const long long sSS = (long long)SS * SS;

    // 0) weight converts (single launch)
    wconv4_kernel<<<256, 256>>>(Wq, Wk, Wv, Wo, wh);

    // 1) GroupNorm stats + normalize/transpose -> t [B,S,C] fp16
    gn_stats_kernel<<<BB * NGRP, 256>>>(x, stats);
    norm_t_kernel<<<dim3(SS / 32, CC / 32, BB), dim3(32, 8)>>>(x, stats, gnw, gnb, th);

    // 2) Q, K projections (fp16 [B,S,C]); V projection written transposed [B,C,S]
    dim3 gqkv(CC / 256, SS / 128, BB);
    gemm_mma<1><<<gqkv, 256, SMEM>>>(th, wh + 0 * CC * CC, bq, nullptr, nullptr, qh,
                                     CC, CC, CC, CC, sSC, 0, sSC, 1.f);
    gemm_mma<1><<<gqkv, 256, SMEM>>>(th, wh + 1 * CC * CC, bk, nullptr, nullptr, kh,
                                     CC, CC, CC, CC, sSC, 0, sSC, 1.f);
    gemm_mma<2><<<gqkv, 256, SMEM>>>(th, wh + 2 * CC * CC, bv, nullptr, nullptr, vth,
                                     CC, CC, CC, SS, sSC, 0, sSC, 1.f);

    // 3) scores = SCALE * q k^T (fp32)
    dim3 gsc(SS / 256, SS / 128, BB);
    gemm_mma<0><<<gsc, 256, SMEM>>>(qh, kh, nullptr, nullptr, sc, nullptr,
                                    CC, CC, CC, SS, sSC, sSC, sSS, SCALE_QK);

    // 4) softmax -> P fp16
    softmax_kernel<<<BB * SS, 256>>>(sc, ph);

    // 5) o = P v (fp16 [B,S,C])
    dim3 gpv(CC / 256, SS / 128, BB);
    gemm_mma<1><<<gpv, 256, SMEM>>>(ph, vth, nullptr, nullptr, nullptr, oh,
                                    SS, SS, SS, CC, sSS, sSC, sSC, 1.f);

    // 6) out[b,c,s] = (o Wo^T + bo)^T + x   (fused transpose + residual)
    gemm_mma<3><<<gpv, 256, SMEM>>>(oh, wh + 3 * CC * CC, bo, x, out, nullptr,
                                    CC, CC, CC, SS, sSC, 0, sSC, 1.f);
}

// round 11
// speedup vs baseline: 1.2174x; 1.2174x over previous
#include <cuda_runtime.h>
#include <cuda_fp16.h>
#include <math.h>
#include <stdint.h>

// ---------------------------------------------------------------------------
// AttnBlock via mma.sync HMMA (base sm_100 target).
// Single-pass fp16 GEMMs, fp32 accum.
// R9: back to 128x128 CTA tile / 32x64 warp tile / 2 CTAs/SM (R8's 128x256
// tanked occupancy). New: 4-stage cp.async pipeline with prefetch-3 and a
// SINGLE barrier per K-chunk (4 stages make the trailing barrier redundant).
// ---------------------------------------------------------------------------

#define BB   32
#define CC   512
#define SS   1024
#define NGRP 32
#define CPG  16
#define GELEMS (CPG * SS)
#define SCALE_QK 0.044194173824159216f

typedef __half fp16;

// ------------------------------- scratch ----------------------------------
static __device__ float2 g_stats[BB * NGRP];
static __device__ fp16 g_th [(size_t)BB * SS * CC];
static __device__ fp16 g_qh [(size_t)BB * SS * CC];
static __device__ fp16 g_kh [(size_t)BB * SS * CC];
static __device__ fp16 g_vth[(size_t)BB * CC * SS];
static __device__ float g_s [(size_t)BB * SS * SS];
static __device__ fp16 g_ph [(size_t)BB * SS * SS];
static __device__ fp16 g_oh [(size_t)BB * SS * CC];
static __device__ fp16 g_wh [4 * CC * CC];

// ------------------------------ asm helpers --------------------------------
__device__ __forceinline__ uint32_t smem_u32(const void* p) {
    uint32_t a;
    asm("{ .reg .u64 t; cvta.to.shared.u64 t, %1; cvt.u32.u64 %0, t; }" : "=r"(a) : "l"(p));
    return a;
}
#define CP16(dst, src) \
    asm volatile("cp.async.cg.shared.global [%0], [%1], 16;" :: "r"(dst), "l"(src))
#define CP_COMMIT() asm volatile("cp.async.commit_group;" ::: "memory")
#define CP_WAIT(n)  asm volatile("cp.async.wait_group %0;" :: "n"(n) : "memory")

#define LDSM4(r0, r1, r2, r3, addr) \
    asm volatile("ldmatrix.sync.aligned.m8n8.x4.shared.b16 {%0,%1,%2,%3}, [%4];" \
        : "=r"(r0), "=r"(r1), "=r"(r2), "=r"(r3) : "r"(addr))

#define MMA_FP16(d, a, b) \
    asm volatile("mma.sync.aligned.m16n8k16.row.col.f32.f16.f16.f32 " \
        "{%0,%1,%2,%3}, {%4,%5,%6,%7}, {%8,%9}, {%0,%1,%2,%3};" \
        : "+f"((d)[0]), "+f"((d)[1]), "+f"((d)[2]), "+f"((d)[3]) \
        : "r"((a)[0]), "r"((a)[1]), "r"((a)[2]), "r"((a)[3]), \
          "r"((b)[0]), "r"((b)[1]))

// ---------------------------------------------------------------------------
// Warp-MMA batched GEMM: C[m,n] = alpha*(A[m,:] . B[n,:]) + bias[n]
// A [M,K] row-major fp16, B [N,K] row-major fp16. CTA tile 128x128, BK=32,
// 8 warps (4x2), warp tile 32x64. 4-stage cp.async pipeline (prefetch 3),
// one __syncthreads per chunk. 2 CTAs/SM (128 regs, 81920 B smem).
// OUT_MODE 0: fp32 C[m,n] -> Cf
// OUT_MODE 1: fp16 C[m,n] -> Ch
// OUT_MODE 2: fp16 C^T[n,m] -> Ch           (ldc strides the n dim)
// OUT_MODE 3: fp32 C^T[n,m] + resid -> Cf   (residual add, ldc strides n)
// ---------------------------------------------------------------------------
#define STAGE_B 20480

template<int OUT_MODE>
__global__ void __launch_bounds__(256, 2)
gemm_mma(const fp16* __restrict__ A, const fp16* __restrict__ B,
         const float* __restrict__ bias, const float* __restrict__ resid,
         float* __restrict__ Cf, fp16* __restrict__ Ch,
         int K, int lda, int ldb, int ldc,
         long long sA, long long sB, long long sC, float alpha)
{
    extern __shared__ __align__(16) char smem[];
    const uint32_t sb = smem_u32(smem);
    const int tid = threadIdx.x, wid = tid >> 5, lane = tid & 31;
    const int bm = blockIdx.y * 128, bn = blockIdx.x * 128;

    A += (size_t)blockIdx.z * sA;
    B += (size_t)blockIdx.z * sB;

    const int lrow = tid >> 2;
    const int lseg = tid & 3;

    float acc[2][8][4];
    #pragma unroll
    for (int i = 0; i < 2; i++)
        #pragma unroll
        for (int j = 0; j < 8; j++)
            #pragma unroll
            for (int t = 0; t < 4; t++) acc[i][j][t] = 0.f;

    auto load_stage = [&](int k0, int buf) {
        const uint32_t base = sb + buf * STAGE_B;
        #pragma unroll
        for (int half = 0; half < 2; half++) {
            const int r = lrow + half * 64;
            const uint32_t doff = (uint32_t)(r * 80 + lseg * 16);
            CP16(base +         doff, A + (size_t)(bm + r) * lda + k0 + lseg * 8);
            CP16(base + 10240 + doff, B + (size_t)(bn + r) * ldb + k0 + lseg * 8);
        }
    };

    const int m0 = (wid & 3) * 32, n0 = (wid >> 2) * 64;
    const int arow = (lane & 7) + ((lane >> 3) & 1) * 8;
    const int acol = (lane >> 4) * 8;
    const int brow = (lane & 7) + (lane >> 4) * 8;
    const int bcol = ((lane >> 3) & 1) * 8;

    const int NC = K >> 5;
    load_stage(0, 0);  CP_COMMIT();
    load_stage(32, 1); CP_COMMIT();
    load_stage(64, 2); CP_COMMIT();

    for (int c = 0; c < NC; c++) {
        const int rem = NC - 1 - c;       // groups committed after group c
        if (rem >= 2)      { CP_WAIT(2); }
        else if (rem == 1) { CP_WAIT(1); }
        else               { CP_WAIT(0); }
        __syncthreads();                   // single barrier per chunk
        if (c + 3 < NC) {
            load_stage((c + 3) << 5, (c + 3) & 3);
            CP_COMMIT();
        }

        const uint32_t st = sb + (c & 3) * STAGE_B;
        #pragma unroll
        for (int kx = 0; kx < 32; kx += 16) {
            uint32_t fa[2][4];
            uint32_t fb[8][2];
            #pragma unroll
            for (int mt = 0; mt < 2; mt++) {
                const uint32_t ad = st +
                    (uint32_t)(((m0 + mt * 16 + arow) * 40 + kx + acol) * 2);
                LDSM4(fa[mt][0], fa[mt][1], fa[mt][2], fa[mt][3], ad);
            }
            #pragma unroll
            for (int p = 0; p < 4; p++) {
                const uint32_t bd = st + 10240 +
                    (uint32_t)(((n0 + p * 16 + brow) * 40 + kx + bcol) * 2);
                LDSM4(fb[2*p][0], fb[2*p][1], fb[2*p+1][0], fb[2*p+1][1], bd);
            }
            #pragma unroll
            for (int mt = 0; mt < 2; mt++)
                #pragma unroll
                for (int nt = 0; nt < 8; nt++)
                    MMA_FP16(acc[mt][nt], fa[mt], fb[nt]);
        }
        // no trailing barrier: with 4 stages, the next write to this buffer
        // happens behind the NEXT iteration's barrier (see header comment).
    }
    __syncthreads();

    // ------------------------------ epilogue -------------------------------
    if (OUT_MODE <= 1) {
        #pragma unroll
        for (int mt = 0; mt < 2; mt++) {
            const int gm = bm + m0 + mt * 16 + (lane >> 2);
            #pragma unroll
            for (int nt = 0; nt < 8; nt++) {
                const int gn = bn + n0 + nt * 8 + 2 * (lane & 3);
                const float b0 = bias ? bias[gn]     : 0.f;
                const float b1 = bias ? bias[gn + 1] : 0.f;
                const float* d = acc[mt][nt];
                const float v00 = d[0] * alpha + b0, v01 = d[1] * alpha + b1;
                const float v10 = d[2] * alpha + b0, v11 = d[3] * alpha + b1;
                const size_t r0 = (size_t)blockIdx.z * sC + (size_t)gm * ldc + gn;
                const size_t r1 = r0 + (size_t)8 * ldc;
                if (OUT_MODE == 0) {
                    *reinterpret_cast<float2*>(&Cf[r0]) = make_float2(v00, v01);
                    *reinterpret_cast<float2*>(&Cf[r1]) = make_float2(v10, v11);
                } else {
                    *reinterpret_cast<__half2*>(&Ch[r0]) =
                        __halves2half2(__float2half(v00), __float2half(v01));
                    *reinterpret_cast<__half2*>(&Ch[r1]) =
                        __halves2half2(__float2half(v10), __float2half(v11));
                }
            }
        }
    } else {
        // Transposed epilogue: 2 halves of 64 n-rows x 128 m-cols via smem.
        float* smt = reinterpret_cast<float*>(smem);      // [64][132] fp32
        const int nhme = wid >> 2;
        #pragma unroll
        for (int nh = 0; nh < 2; nh++) {
            __syncthreads();
            if (nhme == nh) {
                #pragma unroll
                for (int mt = 0; mt < 2; mt++) {
                    const int sl = m0 + mt * 16 + (lane >> 2);
                    #pragma unroll
                    for (int nt = 0; nt < 8; nt++) {
                        const int cl = nt * 8 + 2 * (lane & 3);
                        const float b0 = bias ? bias[bn + nh * 64 + cl]     : 0.f;
                        const float b1 = bias ? bias[bn + nh * 64 + cl + 1] : 0.f;
                        const float* d = acc[mt][nt];
                        smt[cl       * 132 + sl]     = d[0] * alpha + b0;
                        smt[(cl + 1) * 132 + sl]     = d[1] * alpha + b1;
                        smt[cl       * 132 + sl + 8] = d[2] * alpha + b0;
                        smt[(cl + 1) * 132 + sl + 8] = d[3] * alpha + b1;
                    }
                }
            }
            __syncthreads();
            if (OUT_MODE == 2) {
                #pragma unroll
                for (int it = 0; it < 16; it++) {
                    const int idx = tid + it * 256;
                    const int cl = idx >> 6, s2 = (idx & 63) * 2;
                    const size_t o = (size_t)blockIdx.z * sC +
                        (size_t)(bn + nh * 64 + cl) * ldc + bm + s2;
                    *reinterpret_cast<__half2*>(&Ch[o]) = __halves2half2(
                        __float2half(smt[cl * 132 + s2]),
                        __float2half(smt[cl * 132 + s2 + 1]));
                }
            } else {
                #pragma unroll
                for (int it = 0; it < 32; it++) {
                    const int idx = tid + it * 256;
                    const int cl = idx >> 7, sl = idx & 127;
                    const size_t o = (size_t)blockIdx.z * sC +
                        (size_t)(bn + nh * 64 + cl) * ldc + bm + sl;
                    Cf[o] = smt[cl * 132 + sl] + resid[o];
                }
            }
        }
    }
}

// ---------------------------------------------------------------------------
// GroupNorm stats
// ---------------------------------------------------------------------------
__global__ __launch_bounds__(256)
void gn_stats_kernel(const float* __restrict__ x, float2* __restrict__ stats)
{
    const int b = blockIdx.x >> 5, g = blockIdx.x & 31;
    const size_t base = ((size_t)b * CC + (size_t)g * CPG) * SS;
    float s = 0.f, s2 = 0.f;
    for (int i = threadIdx.x * 4; i < GELEMS; i += 1024) {
        float4 v = *reinterpret_cast<const float4*>(&x[base + i]);
        s  += v.x + v.y + v.z + v.w;
        s2 += v.x * v.x + v.y * v.y + v.z * v.z + v.w * v.w;
    }
    #pragma unroll
    for (int o = 16; o; o >>= 1) {
        s  += __shfl_xor_sync(0xffffffffu, s, o);
        s2 += __shfl_xor_sync(0xffffffffu, s2, o);
    }
    __shared__ float ws[8], ws2[8];
    if ((threadIdx.x & 31) == 0) { ws[threadIdx.x >> 5] = s; ws2[threadIdx.x >> 5] = s2; }
    __syncthreads();
    if (threadIdx.x == 0) {
        float ts = 0.f, ts2 = 0.f;
        #pragma unroll
        for (int i = 0; i < 8; i++) { ts += ws[i]; ts2 += ws2[i]; }
        const float mu  = ts * (1.f / GELEMS);
        const float var = ts2 * (1.f / GELEMS) - mu * mu;
        stats[blockIdx.x] = make_float2(mu, rsqrtf(var + 1e-6f));
    }
}

// ---------------------------------------------------------------------------
// Normalize + transpose: x[b,c,s] -> t [b,s,c] fp16
// ---------------------------------------------------------------------------
__global__ __launch_bounds__(256)
void norm_t_kernel(const float* __restrict__ x, const float2* __restrict__ stats,
                   const float* __restrict__ w, const float* __restrict__ bgn,
                   fp16* __restrict__ th)
{
    __shared__ float sm[32][33];
    const int b = blockIdx.z, s0 = blockIdx.x * 32, c0 = blockIdx.y * 32;
    const int tx = threadIdx.x, ty = threadIdx.y;
    #pragma unroll
    for (int cy = ty; cy < 32; cy += 8) {
        const int c = c0 + cy;
        const float2 st = stats[b * 32 + (c >> 4)];
        const float v = x[((size_t)b * CC + c) * SS + s0 + tx];
        sm[cy][tx] = (v - st.x) * st.y * w[c] + bgn[c];
    }
    __syncthreads();
    #pragma unroll
    for (int sy = ty; sy < 32; sy += 8)
        th[((size_t)b * SS + s0 + sy) * CC + c0 + tx] = __float2half(sm[tx][sy]);
}

// ---------------------------------------------------------------------------
// Row softmax over 1024 cols; P -> fp16
// ---------------------------------------------------------------------------
__global__ __launch_bounds__(256)
void softmax_kernel(const float* __restrict__ s, fp16* __restrict__ ph)
{
    const size_t ro = (size_t)blockIdx.x * SS;
    float4 v = *reinterpret_cast<const float4*>(&s[ro + threadIdx.x * 4]);

    float m = fmaxf(fmaxf(v.x, v.y), fmaxf(v.z, v.w));
    #pragma unroll
    for (int o = 16; o; o >>= 1) m = fmaxf(m, __shfl_xor_sync(0xffffffffu, m, o));
    __shared__ float redm[8], reds[8];
    const int lane = threadIdx.x & 31, wid = threadIdx.x >> 5;
    if (lane == 0) redm[wid] = m;
    __syncthreads();
    float M = redm[0];
    #pragma unroll
    for (int i = 1; i < 8; i++) M = fmaxf(M, redm[i]);

    v.x = expf(v.x - M); v.y = expf(v.y - M);
    v.z = expf(v.z - M); v.w = expf(v.w - M);
    float sum = v.x + v.y + v.z + v.w;
    #pragma unroll
    for (int o = 16; o; o >>= 1) sum += __shfl_xor_sync(0xffffffffu, sum, o);
    if (lane == 0) reds[wid] = sum;
    __syncthreads();
    float T = 0.f;
    #pragma unroll
    for (int i = 0; i < 8; i++) T += reds[i];
    const float inv = 1.f / T;

    *reinterpret_cast<__half2*>(&ph[ro + threadIdx.x * 4]) =
        __halves2half2(__float2half(v.x * inv), __float2half(v.y * inv));
    *reinterpret_cast<__half2*>(&ph[ro + threadIdx.x * 4 + 2]) =
        __halves2half2(__float2half(v.z * inv), __float2half(v.w * inv));
}

// ---------------------------------------------------------------------------
// All four weight converts in one launch
// ---------------------------------------------------------------------------
__global__ __launch_bounds__(256)
void wconv4_kernel(const float* __restrict__ a, const float* __restrict__ b,
                   const float* __restrict__ c, const float* __restrict__ d,
                   fp16* __restrict__ dst)
{
    const int n = CC * CC;
    for (int i = blockIdx.x * 256 + threadIdx.x; i < n; i += gridDim.x * 256) {
        dst[i]         = __float2half(a[i]);
        dst[n + i]     = __float2half(b[i]);
        dst[2 * n + i] = __float2half(c[i]);
        dst[3 * n + i] = __float2half(d[i]);
    }
}

// ---------------------------------------------------------------------------
// Launch
// ---------------------------------------------------------------------------
extern "C" void kernel_launch(void* const* d_in, const int* in_sizes, int n_in,
                              void* d_out, int out_size)
{
    const float* x   = (const float*)d_in[0];
    const float* gnw = (const float*)d_in[1];
    const float* gnb = (const float*)d_in[2];
    const float* Wq  = (const float*)d_in[3];
    const float* bq  = (const float*)d_in[4];
    const float* Wk  = (const float*)d_in[5];
    const float* bk  = (const float*)d_in[6];
    const float* Wv  = (const float*)d_in[7];
    const float* bv  = (const float*)d_in[8];
    const float* Wo  = (const float*)d_in[9];
    const float* bo  = (const float*)d_in[10];
    float* out = (float*)d_out;

    float2* stats; fp16 *th, *qh, *kh, *vth, *ph, *oh, *wh;
    float *sc;
    cudaGetSymbolAddress((void**)&stats, g_stats);
    cudaGetSymbolAddress((void**)&th,  g_th);
    cudaGetSymbolAddress((void**)&qh,  g_qh);
    cudaGetSymbolAddress((void**)&kh,  g_kh);
    cudaGetSymbolAddress((void**)&vth, g_vth);
    cudaGetSymbolAddress((void**)&sc,  g_s);
    cudaGetSymbolAddress((void**)&ph,  g_ph);
    cudaGetSymbolAddress((void**)&oh,  g_oh);
    cudaGetSymbolAddress((void**)&wh,  g_wh);

    const int SMEM = 4 * STAGE_B;   // 81920 B (>= 64*132*4 epilogue tile)
    cudaFuncSetAttribute(gemm_mma<0>, cudaFuncAttributeMaxDynamicSharedMemorySize, SMEM);
    cudaFuncSetAttribute(gemm_mma<1>, cudaFuncAttributeMaxDynamicSharedMemorySize, SMEM);
    cudaFuncSetAttribute(gemm_mma<2>, cudaFuncAttributeMaxDynamicSharedMemorySize, SMEM);
    cudaFuncSetAttribute(gemm_mma<3>, cudaFuncAttributeMaxDynamicSharedMemorySize, SMEM);

    const long long sSC = (long long)SS * CC;
    const long long sSS = (long long)SS * SS;

    // 0) weight converts (single launch)
    wconv4_kernel<<<256, 256>>>(Wq, Wk, Wv, Wo, wh);

    // 1) GroupNorm stats + normalize/transpose -> t [B,S,C] fp16
    gn_stats_kernel<<<BB * NGRP, 256>>>(x, stats);
    norm_t_kernel<<<dim3(SS / 32, CC / 32, BB), dim3(32, 8)>>>(x, stats, gnw, gnb, th);

    // 2) Q, K projections (fp16 [B,S,C]); V projection written transposed [B,C,S]
    dim3 gqkv(CC / 128, SS / 128, BB);
    gemm_mma<1><<<gqkv, 256, SMEM>>>(th, wh + 0 * CC * CC, bq, nullptr, nullptr, qh,
                                     CC, CC, CC, CC, sSC, 0, sSC, 1.f);
    gemm_mma<1><<<gqkv, 256, SMEM>>>(th, wh + 1 * CC * CC, bk, nullptr, nullptr, kh,
                                     CC, CC, CC, CC, sSC, 0, sSC, 1.f);
    gemm_mma<2><<<gqkv, 256, SMEM>>>(th, wh + 2 * CC * CC, bv, nullptr, nullptr, vth,
                                     CC, CC, CC, SS, sSC, 0, sSC, 1.f);

    // 3) scores = SCALE * q k^T (fp32)
    dim3 gsc(SS / 128, SS / 128, BB);
    gemm_mma<0><<<gsc, 256, SMEM>>>(qh, kh, nullptr, nullptr, sc, nullptr,
                                    CC, CC, CC, SS, sSC, sSC, sSS, SCALE_QK);

    // 4) softmax -> P fp16
    softmax_kernel<<<BB * SS, 256>>>(sc, ph);

    // 5) o = P v (fp16 [B,S,C])
    dim3 gpv(CC / 128, SS / 128, BB);
    gemm_mma<1><<<gpv, 256, SMEM>>>(ph, vth, nullptr, nullptr, nullptr, oh,
                                    SS, SS, SS, CC, sSS, sSC, sSC, 1.f);

    // 6) out[b,c,s] = (o Wo^T + bo)^T + x   (fused transpose + residual)
    gemm_mma<3><<<gpv, 256, SMEM>>>(oh, wh + 3 * CC * CC, bo, x, out, nullptr,
                                    CC, CC, CC, SS, sSC, 0, sSC, 1.f);
}

// round 13
// speedup vs baseline: 1.2831x; 1.0540x over previous
#include <cuda_runtime.h>
#include <cuda_fp16.h>
#include <math.h>
#include <stdint.h>

// ---------------------------------------------------------------------------
// AttnBlock via mma.sync HMMA (base sm_100 target).
// Single-pass fp16 GEMMs, fp32 accum. HMMA path is saturated (~45% of the
// tcgen05-normalized tensor peak across all R7-R11 variants) => R12 attacks
// non-GEMM time: fused GroupNorm (1 pass over x), QKV merged into one
// launch, fp16 scores (halves softmax round-trip traffic).
// ---------------------------------------------------------------------------

#define BB   32
#define CC   512
#define SS   1024
#define NGRP 32
#define CPG  16
#define SCALE_QK 0.044194173824159216f

typedef __half fp16;

// ------------------------------- scratch ----------------------------------
static __device__ fp16 g_th [(size_t)BB * SS * CC];
static __device__ fp16 g_qh [(size_t)BB * SS * CC];
static __device__ fp16 g_kh [(size_t)BB * SS * CC];
static __device__ fp16 g_vth[(size_t)BB * CC * SS];
static __device__ fp16 g_sc [(size_t)BB * SS * SS];   // fp16 scores
static __device__ fp16 g_ph [(size_t)BB * SS * SS];
static __device__ fp16 g_oh [(size_t)BB * SS * CC];
static __device__ fp16 g_wh [4 * CC * CC];

// ------------------------------ asm helpers --------------------------------
__device__ __forceinline__ uint32_t smem_u32(const void* p) {
    uint32_t a;
    asm("{ .reg .u64 t; cvta.to.shared.u64 t, %1; cvt.u32.u64 %0, t; }" : "=r"(a) : "l"(p));
    return a;
}
#define CP16(dst, src) \
    asm volatile("cp.async.cg.shared.global [%0], [%1], 16;" :: "r"(dst), "l"(src))
#define CP_COMMIT() asm volatile("cp.async.commit_group;" ::: "memory")
#define CP_WAIT(n)  asm volatile("cp.async.wait_group %0;" :: "n"(n) : "memory")

#define LDSM4(r0, r1, r2, r3, addr) \
    asm volatile("ldmatrix.sync.aligned.m8n8.x4.shared.b16 {%0,%1,%2,%3}, [%4];" \
        : "=r"(r0), "=r"(r1), "=r"(r2), "=r"(r3) : "r"(addr))

#define MMA_FP16(d, a, b) \
    asm volatile("mma.sync.aligned.m16n8k16.row.col.f32.f16.f16.f32 " \
        "{%0,%1,%2,%3}, {%4,%5,%6,%7}, {%8,%9}, {%0,%1,%2,%3};" \
        : "+f"((d)[0]), "+f"((d)[1]), "+f"((d)[2]), "+f"((d)[3]) \
        : "r"((a)[0]), "r"((a)[1]), "r"((a)[2]), "r"((a)[3]), \
          "r"((b)[0]), "r"((b)[1]))

#define STAGE_B 20480

// ---------------------------------------------------------------------------
// Shared GEMM mainloop (128x128 tile, BK=32, 8 warps 4x2, 4-stage cp.async,
// single barrier/chunk, 2 CTAs/SM). Produces acc[2][8][4].
// ---------------------------------------------------------------------------
#define GEMM_MAINLOOP(Aptr, Bptr, bm_, bn_, lda_, ldb_, Kval)                 \
    const uint32_t sb = smem_u32(smem);                                       \
    const int tid = threadIdx.x, wid = tid >> 5, lane = tid & 31;             \
    const int lrow = tid >> 2, lseg = tid & 3;                                \
    float acc[2][8][4];                                                       \
    _Pragma("unroll")                                                         \
    for (int i = 0; i < 2; i++)                                               \
        _Pragma("unroll")                                                     \
        for (int j = 0; j < 8; j++)                                           \
            _Pragma("unroll")                                                 \
            for (int t = 0; t < 4; t++) acc[i][j][t] = 0.f;                   \
    auto load_stage = [&](int k0, int buf) {                                  \
        const uint32_t base = sb + buf * STAGE_B;                             \
        _Pragma("unroll")                                                     \
        for (int half = 0; half < 2; half++) {                                \
            const int r = lrow + half * 64;                                   \
            const uint32_t doff = (uint32_t)(r * 80 + lseg * 16);             \
            CP16(base +         doff, (Aptr) + (size_t)((bm_) + r) * (lda_) + k0 + lseg * 8); \
            CP16(base + 10240 + doff, (Bptr) + (size_t)((bn_) + r) * (ldb_) + k0 + lseg * 8); \
        }                                                                     \
    };                                                                        \
    const int m0 = (wid & 3) * 32, n0 = (wid >> 2) * 64;                      \
    const int arow = (lane & 7) + ((lane >> 3) & 1) * 8;                      \
    const int acol = (lane >> 4) * 8;                                         \
    const int brow = (lane & 7) + (lane >> 4) * 8;                            \
    const int bcol = ((lane >> 3) & 1) * 8;                                   \
    const int NC = (Kval) >> 5;                                               \
    load_stage(0, 0);  CP_COMMIT();                                           \
    load_stage(32, 1); CP_COMMIT();                                           \
    load_stage(64, 2); CP_COMMIT();                                           \
    for (int c = 0; c < NC; c++) {                                            \
        const int rem = NC - 1 - c;                                           \
        if (rem >= 2)      { CP_WAIT(2); }                                    \
        else if (rem == 1) { CP_WAIT(1); }                                    \
        else               { CP_WAIT(0); }                                    \
        __syncthreads();                                                      \
        if (c + 3 < NC) { load_stage((c + 3) << 5, (c + 3) & 3); CP_COMMIT(); } \
        const uint32_t st = sb + (c & 3) * STAGE_B;                           \
        _Pragma("unroll")                                                     \
        for (int kx = 0; kx < 32; kx += 16) {                                 \
            uint32_t fa[2][4];                                                \
            uint32_t fb[8][2];                                                \
            _Pragma("unroll")                                                 \
            for (int mt = 0; mt < 2; mt++) {                                  \
                const uint32_t ad = st +                                      \
                    (uint32_t)(((m0 + mt * 16 + arow) * 40 + kx + acol) * 2); \
                LDSM4(fa[mt][0], fa[mt][1], fa[mt][2], fa[mt][3], ad);        \
            }                                                                 \
            _Pragma("unroll")                                                 \
            for (int p = 0; p < 4; p++) {                                     \
                const uint32_t bd = st + 10240 +                              \
                    (uint32_t)(((n0 + p * 16 + brow) * 40 + kx + bcol) * 2);  \
                LDSM4(fb[2*p][0], fb[2*p][1], fb[2*p+1][0], fb[2*p+1][1], bd);\
            }                                                                 \
            _Pragma("unroll")                                                 \
            for (int mt = 0; mt < 2; mt++)                                    \
                _Pragma("unroll")                                             \
                for (int nt = 0; nt < 8; nt++)                                \
                    MMA_FP16(acc[mt][nt], fa[mt], fb[nt]);                    \
        }                                                                     \
    }                                                                         \
    __syncthreads();

// Normal fp16 epilogue (C[m,n])
#define EPI_FP16(Ch, bias_, bm_, bn_, ldc_, sC_, alpha_)                      \
    _Pragma("unroll")                                                         \
    for (int mt = 0; mt < 2; mt++) {                                          \
        const int gm = (bm_) + m0 + mt * 16 + (lane >> 2);                    \
        _Pragma("unroll")                                                     \
        for (int nt = 0; nt < 8; nt++) {                                      \
            const int gn = (bn_) + n0 + nt * 8 + 2 * (lane & 3);              \
            const float b0 = (bias_) ? (bias_)[gn]     : 0.f;                 \
            const float b1 = (bias_) ? (bias_)[gn + 1] : 0.f;                 \
            const float* d = acc[mt][nt];                                     \
            const size_t r0 = (size_t)blockIdx.z * (sC_) + (size_t)gm * (ldc_) + gn; \
            const size_t r1 = r0 + (size_t)8 * (ldc_);                        \
            *reinterpret_cast<__half2*>(&(Ch)[r0]) = __halves2half2(          \
                __float2half(d[0] * (alpha_) + b0), __float2half(d[1] * (alpha_) + b1)); \
            *reinterpret_cast<__half2*>(&(Ch)[r1]) = __halves2half2(          \
                __float2half(d[2] * (alpha_) + b0), __float2half(d[3] * (alpha_) + b1)); \
        }                                                                     \
    }

// Transposed epilogue via smem stage: writes C^T[n,m] (fp16) or fp32+resid
#define EPI_TRANS(IS_F32, Ch, Cf, bias_, resid_, bm_, bn_, ldc_, sC_, alpha_) \
    {                                                                         \
    float* smt = reinterpret_cast<float*>(smem);                              \
    const int nhme = wid >> 2;                                                \
    _Pragma("unroll")                                                         \
    for (int nh = 0; nh < 2; nh++) {                                          \
        __syncthreads();                                                      \
        if (nhme == nh) {                                                     \
            _Pragma("unroll")                                                 \
            for (int mt = 0; mt < 2; mt++) {                                  \
                const int sl = m0 + mt * 16 + (lane >> 2);                    \
                _Pragma("unroll")                                             \
                for (int nt = 0; nt < 8; nt++) {                              \
                    const int cl = nt * 8 + 2 * (lane & 3);                   \
                    const float b0 = (bias_) ? (bias_)[(bn_) + nh * 64 + cl]     : 0.f; \
                    const float b1 = (bias_) ? (bias_)[(bn_) + nh * 64 + cl + 1] : 0.f; \
                    const float* d = acc[mt][nt];                             \
                    smt[cl       * 132 + sl]     = d[0] * (alpha_) + b0;      \
                    smt[(cl + 1) * 132 + sl]     = d[1] * (alpha_) + b1;      \
                    smt[cl       * 132 + sl + 8] = d[2] * (alpha_) + b0;      \
                    smt[(cl + 1) * 132 + sl + 8] = d[3] * (alpha_) + b1;      \
                }                                                             \
            }                                                                 \
        }                                                                     \
        __syncthreads();                                                      \
        if (!(IS_F32)) {                                                      \
            _Pragma("unroll")                                                 \
            for (int it = 0; it < 16; it++) {                                 \
                const int idx = tid + it * 256;                               \
                const int cl = idx >> 6, s2 = (idx & 63) * 2;                 \
                const size_t o = (size_t)blockIdx.z * (sC_) +                 \
                    (size_t)((bn_) + nh * 64 + cl) * (ldc_) + (bm_) + s2;     \
                *reinterpret_cast<__half2*>(&(Ch)[o]) = __halves2half2(       \
                    __float2half(smt[cl * 132 + s2]),                         \
                    __float2half(smt[cl * 132 + s2 + 1]));                    \
            }                                                                 \
        } else {                                                              \
            _Pragma("unroll")                                                 \
            for (int it = 0; it < 32; it++) {                                 \
                const int idx = tid + it * 256;                               \
                const int cl = idx >> 7, sl = idx & 127;                      \
                const size_t o = (size_t)blockIdx.z * (sC_) +                 \
                    (size_t)((bn_) + nh * 64 + cl) * (ldc_) + (bm_) + sl;     \
                (Cf)[o] = smt[cl * 132 + sl] + (resid_)[o];                   \
            }                                                                 \
        }                                                                     \
    }                                                                         \
    }

// ---------------------------------------------------------------------------
// Fused QKV: grid.x in [0,12): sel = x>>2 picks Q/K/V, bn = (x&3)*128.
// Q,K -> fp16 [B,S,C]; V -> transposed fp16 [B,C,S].
// ---------------------------------------------------------------------------
__global__ void __launch_bounds__(256, 2)
qkv_mma(const fp16* __restrict__ T, const fp16* __restrict__ W,
        const float* __restrict__ bq, const float* __restrict__ bk,
        const float* __restrict__ bv,
        fp16* __restrict__ Q, fp16* __restrict__ Kout, fp16* __restrict__ VT)
{
    extern __shared__ __align__(16) char smem[];
    const int sel = blockIdx.x >> 2;
    const int bm = blockIdx.y * 128, bn = (blockIdx.x & 3) * 128;
    const fp16* A = T + (size_t)blockIdx.z * SS * CC;
    const fp16* B = W + (size_t)sel * CC * CC;

    GEMM_MAINLOOP(A, B, bm, bn, CC, CC, CC)

    const long long sSC = (long long)SS * CC;
    if (sel == 0) {
        EPI_FP16(Q, bq, bm, bn, CC, sSC, 1.f)
    } else if (sel == 1) {
        EPI_FP16(Kout, bk, bm, bn, CC, sSC, 1.f)
    } else {
        EPI_TRANS(false, VT, (float*)nullptr, bv, (const float*)nullptr,
                  bm, bn, SS, sSC, 1.f)
    }
}

// ---------------------------------------------------------------------------
// Generic GEMM, fp16 out (used for scores with alpha, and P*V)
// ---------------------------------------------------------------------------
__global__ void __launch_bounds__(256, 2)
gemm_h(const fp16* __restrict__ Ain, const fp16* __restrict__ Bin,
       const float* __restrict__ bias, fp16* __restrict__ Ch,
       int K, int lda, int ldb, int ldc,
       long long sA, long long sB, long long sC, float alpha)
{
    extern __shared__ __align__(16) char smem[];
    const int bm = blockIdx.y * 128, bn = blockIdx.x * 128;
    const fp16* A = Ain + (size_t)blockIdx.z * sA;
    const fp16* B = Bin + (size_t)blockIdx.z * sB;

    GEMM_MAINLOOP(A, B, bm, bn, lda, ldb, K)
    EPI_FP16(Ch, bias, bm, bn, ldc, sC, alpha)
}

// ---------------------------------------------------------------------------
// Final GEMM: out[b,c,s] = (o Wo^T + bo)^T + x
// ---------------------------------------------------------------------------
__global__ void __launch_bounds__(256, 2)
gemm_final(const fp16* __restrict__ O, const fp16* __restrict__ W,
           const float* __restrict__ bo, const float* __restrict__ X,
           float* __restrict__ Out)
{
    extern __shared__ __align__(16) char smem[];
    const int bm = blockIdx.y * 128, bn = blockIdx.x * 128;
    const fp16* A = O + (size_t)blockIdx.z * SS * CC;
    const fp16* B = W;

    GEMM_MAINLOOP(A, B, bm, bn, CC, CC, CC)

    const long long sCS = (long long)CC * SS;
    EPI_TRANS(true, (fp16*)nullptr, Out, bo, X, bm, bn, SS, sCS, 1.f)
}

// ---------------------------------------------------------------------------
// Fused GroupNorm: one block per (b,g); 1024 threads (one per s), 16 c each.
// Reads x once, writes normalized+transposed fp16 t[b,s,c].
// ---------------------------------------------------------------------------
__global__ __launch_bounds__(1024)
void gn_fused_kernel(const float* __restrict__ x, const float* __restrict__ w,
                     const float* __restrict__ bgn, fp16* __restrict__ th)
{
    const int b = blockIdx.x >> 5, g = blockIdx.x & 31;
    const size_t base = ((size_t)b * CC + (size_t)g * CPG) * SS;
    const int t = threadIdx.x;           // s index

    float v[CPG];
    float s = 0.f, s2 = 0.f;
    #pragma unroll
    for (int c = 0; c < CPG; c++) {
        v[c] = x[base + (size_t)c * SS + t];
        s += v[c]; s2 += v[c] * v[c];
    }
    #pragma unroll
    for (int o = 16; o; o >>= 1) {
        s  += __shfl_xor_sync(0xffffffffu, s, o);
        s2 += __shfl_xor_sync(0xffffffffu, s2, o);
    }
    __shared__ float ws[32], ws2[32];
    __shared__ float s_mu, s_inv;
    const int lane = t & 31, wrp = t >> 5;
    if (lane == 0) { ws[wrp] = s; ws2[wrp] = s2; }
    __syncthreads();
    if (wrp == 0) {
        float a = ws[lane], a2 = ws2[lane];
        #pragma unroll
        for (int o = 16; o; o >>= 1) {
            a  += __shfl_xor_sync(0xffffffffu, a, o);
            a2 += __shfl_xor_sync(0xffffffffu, a2, o);
        }
        if (lane == 0) {
            const float inv_n = 1.f / (CPG * SS);
            const float mu = a * inv_n;
            s_mu = mu;
            s_inv = rsqrtf(a2 * inv_n - mu * mu + 1e-6f);
        }
    }
    __syncthreads();
    const float mu = s_mu, inv = s_inv;

    __half2 o8[CPG / 2];
    #pragma unroll
    for (int c = 0; c < CPG; c += 2) {
        const int cc0 = g * CPG + c;
        o8[c / 2] = __halves2half2(
            __float2half((v[c]     - mu) * inv * w[cc0]     + bgn[cc0]),
            __float2half((v[c + 1] - mu) * inv * w[cc0 + 1] + bgn[cc0 + 1]));
    }
    fp16* dst = th + ((size_t)b * SS + t) * CC + g * CPG;
    reinterpret_cast<uint4*>(dst)[0] = reinterpret_cast<uint4*>(o8)[0];
    reinterpret_cast<uint4*>(dst)[1] = reinterpret_cast<uint4*>(o8)[1];
}

// ---------------------------------------------------------------------------
// Row softmax over 1024 fp16 logits; P -> fp16
// ---------------------------------------------------------------------------
__global__ __launch_bounds__(256)
void softmax_kernel(const fp16* __restrict__ s, fp16* __restrict__ ph)
{
    const size_t ro = (size_t)blockIdx.x * SS;
    const __half2 h0 = reinterpret_cast<const __half2*>(&s[ro])[threadIdx.x * 2];
    const __half2 h1 = reinterpret_cast<const __half2*>(&s[ro])[threadIdx.x * 2 + 1];
    float4 v = make_float4(__low2float(h0), __high2float(h0),
                           __low2float(h1), __high2float(h1));

    float m = fmaxf(fmaxf(v.x, v.y), fmaxf(v.z, v.w));
    #pragma unroll
    for (int o = 16; o; o >>= 1) m = fmaxf(m, __shfl_xor_sync(0xffffffffu, m, o));
    __shared__ float redm[8], reds[8];
    const int lane = threadIdx.x & 31, wid = threadIdx.x >> 5;
    if (lane == 0) redm[wid] = m;
    __syncthreads();
    float M = redm[0];
    #pragma unroll
    for (int i = 1; i < 8; i++) M = fmaxf(M, redm[i]);

    v.x = expf(v.x - M); v.y = expf(v.y - M);
    v.z = expf(v.z - M); v.w = expf(v.w - M);
    float sum = v.x + v.y + v.z + v.w;
    #pragma unroll
    for (int o = 16; o; o >>= 1) sum += __shfl_xor_sync(0xffffffffu, sum, o);
    if (lane == 0) reds[wid] = sum;
    __syncthreads();
    float T = 0.f;
    #pragma unroll
    for (int i = 0; i < 8; i++) T += reds[i];
    const float inv = 1.f / T;

    *reinterpret_cast<__half2*>(&ph[ro + threadIdx.x * 4]) =
        __halves2half2(__float2half(v.x * inv), __float2half(v.y * inv));
    *reinterpret_cast<__half2*>(&ph[ro + threadIdx.x * 4 + 2]) =
        __halves2half2(__float2half(v.z * inv), __float2half(v.w * inv));
}

// ---------------------------------------------------------------------------
// All four weight converts in one launch (float2 -> half2 vectorized)
// ---------------------------------------------------------------------------
__global__ __launch_bounds__(256)
void wconv4_kernel(const float* __restrict__ a, const float* __restrict__ b,
                   const float* __restrict__ c, const float* __restrict__ d,
                   fp16* __restrict__ dst)
{
    const int n2 = CC * CC / 2;
    for (int i = blockIdx.x * 256 + threadIdx.x; i < n2; i += gridDim.x * 256) {
        const float2 va = reinterpret_cast<const float2*>(a)[i];
        const float2 vb = reinterpret_cast<const float2*>(b)[i];
        const float2 vc = reinterpret_cast<const float2*>(c)[i];
        const float2 vd = reinterpret_cast<const float2*>(d)[i];
        reinterpret_cast<__half2*>(dst)[i]          = __floats2half2_rn(va.x, va.y);
        reinterpret_cast<__half2*>(dst)[n2 + i]     = __floats2half2_rn(vb.x, vb.y);
        reinterpret_cast<__half2*>(dst)[2 * n2 + i] = __floats2half2_rn(vc.x, vc.y);
        reinterpret_cast<__half2*>(dst)[3 * n2 + i] = __floats2half2_rn(vd.x, vd.y);
    }
}

// ---------------------------------------------------------------------------
// Launch
// ---------------------------------------------------------------------------
extern "C" void kernel_launch(void* const* d_in, const int* in_sizes, int n_in,
                              void* d_out, int out_size)
{
    const float* x   = (const float*)d_in[0];
    const float* gnw = (const float*)d_in[1];
    const float* gnb = (const float*)d_in[2];
    const float* bq  = (const float*)d_in[4];
    const float* bk  = (const float*)d_in[6];
    const float* bv  = (const float*)d_in[8];
    const float* Wo  = (const float*)d_in[9];
    const float* bo  = (const float*)d_in[10];
    const float* Wq  = (const float*)d_in[3];
    const float* Wk  = (const float*)d_in[5];
    const float* Wv  = (const float*)d_in[7];
    float* out = (float*)d_out;

    fp16 *th, *qh, *kh, *vth, *sc, *ph, *oh, *wh;
    cudaGetSymbolAddress((void**)&th,  g_th);
    cudaGetSymbolAddress((void**)&qh,  g_qh);
    cudaGetSymbolAddress((void**)&kh,  g_kh);
    cudaGetSymbolAddress((void**)&vth, g_vth);
    cudaGetSymbolAddress((void**)&sc,  g_sc);
    cudaGetSymbolAddress((void**)&ph,  g_ph);
    cudaGetSymbolAddress((void**)&oh,  g_oh);
    cudaGetSymbolAddress((void**)&wh,  g_wh);

    const int SMEM = 4 * STAGE_B;   // 81920 B
    cudaFuncSetAttribute(qkv_mma,    cudaFuncAttributeMaxDynamicSharedMemorySize, SMEM);
    cudaFuncSetAttribute(gemm_h,     cudaFuncAttributeMaxDynamicSharedMemorySize, SMEM);
    cudaFuncSetAttribute(gemm_final, cudaFuncAttributeMaxDynamicSharedMemorySize, SMEM);

    const long long sSC = (long long)SS * CC;
    const long long sSS = (long long)SS * SS;

    // 0) weight converts (single launch)
    wconv4_kernel<<<256, 256>>>(Wq, Wk, Wv, Wo, wh);

    // 1) fused GroupNorm: stats + normalize + transpose -> t [B,S,C] fp16
    gn_fused_kernel<<<BB * NGRP, 1024>>>(x, gnw, gnb, th);

    // 2) fused QKV (one launch): Q,K [B,S,C]; V transposed [B,C,S]
    qkv_mma<<<dim3(12, SS / 128, BB), 256, SMEM>>>(th, wh, bq, bk, bv, qh, kh, vth);

    // 3) scores = SCALE * q k^T  (fp16 out)
    gemm_h<<<dim3(SS / 128, SS / 128, BB), 256, SMEM>>>(
        qh, kh, nullptr, sc, CC, CC, CC, SS, sSC, sSC, sSS, SCALE_QK);

    // 4) softmax (fp16 in) -> P fp16
    softmax_kernel<<<BB * SS, 256>>>(sc, ph);

    // 5) o = P v (fp16 [B,S,C])
    gemm_h<<<dim3(CC / 128, SS / 128, BB), 256, SMEM>>>(
        ph, vth, nullptr, oh, SS, SS, SS, CC, sSS, sSC, sSC, 1.f);

    // 6) out[b,c,s] = (o Wo^T + bo)^T + x   (fused transpose + residual)
    gemm_final<<<dim3(CC / 128, SS / 128, BB), 256, SMEM>>>(oh, wh + 3 * CC * CC, bo, x, out);
}